// round 1
// baseline (speedup 1.0000x reference)
#include <cuda_runtime.h>

#define TSEQ 1024
#define BATCH 4096

__device__ __forceinline__ float ex2_approx(float x) {
    float y; asm("ex2.approx.f32 %0, %1;" : "=f"(y) : "f"(x)); return y;
}
__device__ __forceinline__ float rcp_approx(float x) {
    float y; asm("rcp.approx.f32 %0, %1;" : "=f"(y) : "f"(x)); return y;
}
// tanh(x) = 1 - 2/(exp(2x)+1). ex2/rcp approx err ~2^-22 -> abs err ~1e-6.
// Saturates correctly: x>>0 -> e=inf -> rcp=0 -> 1; x<<0 -> e=0 -> -1.
__device__ __forceinline__ float tanh_fast(float x) {
    float e = ex2_approx(x * 2.8853900817779268f);  // exp(2x) = 2^(x*2*log2(e))
    return fmaf(-2.0f, rcp_approx(e + 1.0f), 1.0f);
}

__global__ __launch_bounds__(128, 1)
void reac_kernel(
    const float* __restrict__ u,    const float* __restrict__ xz0,
    const float* __restrict__ r1W0, const float* __restrict__ r1b0,
    const float* __restrict__ r1W1, const float* __restrict__ r1b1,
    const float* __restrict__ r1W2, const float* __restrict__ r1b2,
    const float* __restrict__ r2W0, const float* __restrict__ r2b0,
    const float* __restrict__ r2W1, const float* __restrict__ r2b1,
    const float* __restrict__ r2W2, const float* __restrict__ r2b2,
    const float* __restrict__ ymean, const float* __restrict__ ystd,
    const float* __restrict__ umean, const float* __restrict__ ustd,
    float* __restrict__ out)
{
    // W1 matrices (16x16, row-major [i][j]) in shared; read as broadcast LDS.128.
    __shared__ float sW1a[256];
    __shared__ float sW1b[256];
    const int tid = threadIdx.x;
    for (int k = tid; k < 256; k += 128) { sW1a[k] = r1W1[k]; sW1b[k] = r2W1[k]; }
    __syncthreads();

    const int g = tid & 3;                       // lane within 4-lane group
    const int e = blockIdx.x * 32 + (tid >> 2);  // batch element (4096 total)

    // Per-lane weight slices: lane g owns hidden units j in [4g, 4g+4).
    float w0a[4], b0a[4], b1a[4], w2a[4];
    float w0b0[4], w0b1[4], b0b[4], b1b[4], w2b[4];
    #pragma unroll
    for (int jj = 0; jj < 4; jj++) {
        int j = g * 4 + jj;
        w0a[jj]  = r1W0[j];      b0a[jj] = r1b0[j];
        b1a[jj]  = r1b1[j];      w2a[jj] = r1W2[j];
        w0b0[jj] = r2W0[j];      w0b1[jj] = r2W0[16 + j];
        b0b[jj]  = r2b0[j];      b1b[jj] = r2b1[j];
        w2b[jj]  = r2W2[j];
    }
    const float b2a = r1b2[0], b2b = r2b2[0];
    const float Castd = ystd[0], Cbstd = ystd[1];
    const float Camean = ymean[0], Cbmean = ymean[1];
    const float us = ustd[0], um = umean[0];
    // Folded epilogue constants (normalized-coordinate dynamics):
    //   dCa_n = uc - 0.1*Ca - f1,            uc = ku*u + kc
    //   dCb_n = kb - 0.1*Cb + kr*f1 - 3*f2
    //   dCc_n = kb - 0.1*Cc + f2
    const float ku = 0.1f * us / Castd;
    const float kc = 0.1f * (um - Camean) / Castd;
    const float kb = -0.1f * Cbmean / Cbstd;
    const float kr = Castd / Cbstd;

    float x0 = xz0[e * 3 + 0], x1 = xz0[e * 3 + 1], x2 = xz0[e * 3 + 2];
    const float* ue = u + (size_t)e * TSEQ;
    float2* ybase = (float2*)(out + (size_t)e * TSEQ * 2);
    float* xbase = out + (size_t)BATCH * TSEQ * 2 + (size_t)e * TSEQ * 3;

    float uc = 0.0f;

    auto fxu = [&](float c0, float c1, float c2, float& d0, float& d1, float& d2) {
        float h[4], acc[4];
        // ---- r1 MLP: scalar input c0 ----
        #pragma unroll
        for (int jj = 0; jj < 4; jj++)
            h[jj] = tanh_fast(fmaf(c0, w0a[jj], b0a[jj]));
        #pragma unroll
        for (int jj = 0; jj < 4; jj++) acc[jj] = b1a[jj];
        #pragma unroll
        for (int s = 0; s < 4; s++) {
            float v[4];
            #pragma unroll
            for (int r = 0; r < 4; r++) v[r] = __shfl_sync(0xffffffffu, h[r], s, 4);
            #pragma unroll
            for (int r = 0; r < 4; r++) {
                const float4 w = *(const float4*)&sW1a[(s * 4 + r) * 16 + g * 4];
                acc[0] = fmaf(v[r], w.x, acc[0]);
                acc[1] = fmaf(v[r], w.y, acc[1]);
                acc[2] = fmaf(v[r], w.z, acc[2]);
                acc[3] = fmaf(v[r], w.w, acc[3]);
            }
        }
        float p1 = 0.0f;
        #pragma unroll
        for (int jj = 0; jj < 4; jj++)
            p1 = fmaf(tanh_fast(acc[jj]), w2a[jj], p1);
        p1 += __shfl_xor_sync(0xffffffffu, p1, 1, 4);
        p1 += __shfl_xor_sync(0xffffffffu, p1, 2, 4);
        const float f1 = p1 + b2a;

        // ---- r2 MLP: inputs (c1, c2) ----
        #pragma unroll
        for (int jj = 0; jj < 4; jj++)
            h[jj] = tanh_fast(fmaf(c2, w0b1[jj], fmaf(c1, w0b0[jj], b0b[jj])));
        #pragma unroll
        for (int jj = 0; jj < 4; jj++) acc[jj] = b1b[jj];
        #pragma unroll
        for (int s = 0; s < 4; s++) {
            float v[4];
            #pragma unroll
            for (int r = 0; r < 4; r++) v[r] = __shfl_sync(0xffffffffu, h[r], s, 4);
            #pragma unroll
            for (int r = 0; r < 4; r++) {
                const float4 w = *(const float4*)&sW1b[(s * 4 + r) * 16 + g * 4];
                acc[0] = fmaf(v[r], w.x, acc[0]);
                acc[1] = fmaf(v[r], w.y, acc[1]);
                acc[2] = fmaf(v[r], w.z, acc[2]);
                acc[3] = fmaf(v[r], w.w, acc[3]);
            }
        }
        float p2 = 0.0f;
        #pragma unroll
        for (int jj = 0; jj < 4; jj++)
            p2 = fmaf(tanh_fast(acc[jj]), w2b[jj], p2);
        p2 += __shfl_xor_sync(0xffffffffu, p2, 1, 4);
        p2 += __shfl_xor_sync(0xffffffffu, p2, 2, 4);
        const float f2 = p2 + b2b;

        d0 = fmaf(-0.1f, c0, uc) - f1;
        d1 = fmaf(kr, f1, fmaf(-3.0f, f2, fmaf(-0.1f, c1, kb)));
        d2 = fmaf(-0.1f, c2, kb) + f2;
    };

    for (int t = 0; t < TSEQ; t++) {
        // Emit pre-update state (scan collects x_t before the step).
        if (g == 0)      ybase[t] = make_float2(x0, x1);
        else if (g == 1) xbase[t * 3 + 0] = x0;
        else if (g == 2) xbase[t * 3 + 1] = x1;
        else             xbase[t * 3 + 2] = x2;

        uc = fmaf(ku, __ldg(&ue[t]), kc);

        float a0, a1, a2, d0, d1, d2, s0, s1, s2;
        fxu(x0, x1, x2, a0, a1, a2);                               // k1
        s0 = fmaf(0.5f, a0, x0); s1 = fmaf(0.5f, a1, x1); s2 = fmaf(0.5f, a2, x2);
        fxu(s0, s1, s2, d0, d1, d2);                               // k2
        a0 = fmaf(2.0f, d0, a0); a1 = fmaf(2.0f, d1, a1); a2 = fmaf(2.0f, d2, a2);
        s0 = fmaf(0.5f, d0, x0); s1 = fmaf(0.5f, d1, x1); s2 = fmaf(0.5f, d2, x2);
        fxu(s0, s1, s2, d0, d1, d2);                               // k3
        a0 = fmaf(2.0f, d0, a0); a1 = fmaf(2.0f, d1, a1); a2 = fmaf(2.0f, d2, a2);
        s0 = x0 + d0; s1 = x1 + d1; s2 = x2 + d2;
        fxu(s0, s1, s2, d0, d1, d2);                               // k4
        a0 += d0; a1 += d1; a2 += d2;
        const float c6 = 1.0f / 6.0f;
        x0 = fmaf(c6, a0, x0); x1 = fmaf(c6, a1, x1); x2 = fmaf(c6, a2, x2);
    }
}

extern "C" void kernel_launch(void* const* d_in, const int* in_sizes, int n_in,
                              void* d_out, int out_size) {
    (void)in_sizes; (void)n_in; (void)out_size;
    reac_kernel<<<128, 128>>>(
        (const float*)d_in[0],  (const float*)d_in[1],
        (const float*)d_in[2],  (const float*)d_in[3],
        (const float*)d_in[4],  (const float*)d_in[5],
        (const float*)d_in[6],  (const float*)d_in[7],
        (const float*)d_in[8],  (const float*)d_in[9],
        (const float*)d_in[10], (const float*)d_in[11],
        (const float*)d_in[12], (const float*)d_in[13],
        (const float*)d_in[14], (const float*)d_in[15],
        (const float*)d_in[16], (const float*)d_in[17],
        (float*)d_out);
}

// round 2
// speedup vs baseline: 1.1106x; 1.1106x over previous
#include <cuda_runtime.h>

#define TSEQ 1024
#define BATCH 4096
#define KTANH 2.885390081777927f   // 2/ln(2): ex2(KTANH*x) = exp(2x)

__device__ __forceinline__ float ex2_approx(float x) {
    float y; asm("ex2.approx.f32 %0, %1;" : "=f"(y) : "f"(x)); return y;
}
__device__ __forceinline__ float rcp_approx(float x) {
    float y; asm("rcp.approx.f32 %0, %1;" : "=f"(y) : "f"(x)); return y;
}
// pre = KTANH*x. Returns r = 1/(exp(2x)+1); tanh(x) = 1 - 2r (the affine is
// folded into downstream weights). Saturation: x>>0 -> r=0; x<<0 -> r=1.
__device__ __forceinline__ float tanh_r(float pre) {
    return rcp_approx(ex2_approx(pre) + 1.0f);
}

__device__ __forceinline__ unsigned long long pack2(float lo, float hi) {
    unsigned long long r;
    asm("mov.b64 %0, {%1, %2};" : "=l"(r) : "f"(lo), "f"(hi)); return r;
}
__device__ __forceinline__ void unpack2(unsigned long long v, float& lo, float& hi) {
    asm("mov.b64 {%0, %1}, %2;" : "=f"(lo), "=f"(hi) : "l"(v));
}
__device__ __forceinline__ unsigned long long fma2(unsigned long long a,
                                                   unsigned long long b,
                                                   unsigned long long c) {
    unsigned long long d;
    asm("fma.rn.f32x2 %0, %1, %2, %3;" : "=l"(d) : "l"(a), "l"(b), "l"(c));
    return d;
}

__global__ __launch_bounds__(128, 1)
void reac_kernel(
    const float* __restrict__ u,    const float* __restrict__ xz0,
    const float* __restrict__ r1W0, const float* __restrict__ r1b0,
    const float* __restrict__ r1W1, const float* __restrict__ r1b1,
    const float* __restrict__ r1W2, const float* __restrict__ r1b2,
    const float* __restrict__ r2W0, const float* __restrict__ r2b0,
    const float* __restrict__ r2W1, const float* __restrict__ r2b1,
    const float* __restrict__ r2W2, const float* __restrict__ r2b2,
    const float* __restrict__ ymean, const float* __restrict__ ystd,
    const float* __restrict__ umean, const float* __restrict__ ustd,
    float* __restrict__ out)
{
    // W1eff = -2*K*W1 (16x16 row-major [i][j]); broadcast LDS.128 reads.
    __shared__ __align__(16) float sW1a[256];
    __shared__ __align__(16) float sW1b[256];
    const int tid = threadIdx.x;
    for (int k = tid; k < 256; k += 128) {
        sW1a[k] = -2.0f * KTANH * r1W1[k];
        sW1b[k] = -2.0f * KTANH * r2W1[k];
    }
    __syncthreads();

    const int g  = tid & 3;                       // lane within 4-lane group
    const int g4 = g * 4;
    const int e  = blockIdx.x * 32 + (tid >> 2);  // batch element

    // Per-lane folded weights: lane g owns hidden units j in [4g, 4g+4).
    float w0aK[4], b0aK[4], w2m2a[4];
    float w0b0K[4], w0b1K[4], b0bK[4], w2m2b[4];
    float b1aK[4], b1bK[4];
    float basea = 0.25f * r1b2[0], baseb = 0.25f * r2b2[0];
    #pragma unroll
    for (int jj = 0; jj < 4; jj++) {
        const int j = g4 + jj;
        w0aK[jj]  = KTANH * r1W0[j];
        b0aK[jj]  = KTANH * r1b0[j];
        w0b0K[jj] = KTANH * r2W0[j];
        w0b1K[jj] = KTANH * r2W0[16 + j];
        b0bK[jj]  = KTANH * r2b0[j];
        float cs1 = 0.0f, cs2 = 0.0f;             // column sums of W1
        for (int i = 0; i < 16; i++) { cs1 += r1W1[i * 16 + j]; cs2 += r2W1[i * 16 + j]; }
        b1aK[jj] = KTANH * (r1b1[j] + cs1);
        b1bK[jj] = KTANH * (r2b1[j] + cs2);
        const float wa2 = r1W2[j], wb2 = r2W2[j];
        basea += wa2;  baseb += wb2;
        w2m2a[jj] = -2.0f * wa2;
        w2m2b[jj] = -2.0f * wb2;
    }
    const unsigned long long b1a01 = pack2(b1aK[0], b1aK[1]);
    const unsigned long long b1a23 = pack2(b1aK[2], b1aK[3]);
    const unsigned long long b1b01 = pack2(b1bK[0], b1bK[1]);
    const unsigned long long b1b23 = pack2(b1bK[2], b1bK[3]);

    const float Castd = ystd[0], Cbstd = ystd[1];
    const float Camean = ymean[0], Cbmean = ymean[1];
    const float us = ustd[0], um = umean[0];
    // Normalized-coordinate dynamics:
    //   dCa = uc - 0.1*Ca - f1,  uc = ku*u + kc
    //   dCb = kb - 0.1*Cb + kr*f1 - 3*f2
    //   dCc = kb - 0.1*Cc + f2
    const float ku = 0.1f * us / Castd;
    const float kc = 0.1f * (um - Camean) / Castd;
    const float kb = -0.1f * Cbmean / Cbstd;
    const float kr = Castd / Cbstd;

    float x0 = xz0[e * 3 + 0], x1 = xz0[e * 3 + 1], x2 = xz0[e * 3 + 2];
    const float* ue = u + (size_t)e * TSEQ;
    float2* ybase = (float2*)(out + (size_t)e * TSEQ * 2);
    float* xbase = out + (size_t)BATCH * TSEQ * 2 + (size_t)e * TSEQ * 3;

    float uc = 0.0f;

    auto fxu = [&](float c0, float c1, float c2, float& d0, float& d1, float& d2) {
        // layer 0 of both MLPs (independent tanh chains)
        float rh[4], sh[4];
        #pragma unroll
        for (int jj = 0; jj < 4; jj++) {
            rh[jj] = tanh_r(fmaf(c0, w0aK[jj], b0aK[jj]));
            sh[jj] = tanh_r(fmaf(c2, w0b1K[jj], fmaf(c1, w0b0K[jj], b0bK[jj])));
        }
        // fused layer-1 matvecs (FFMA2, 8 independent chains)
        unsigned long long accA01 = b1a01, accA23 = b1a23;
        unsigned long long accB01 = b1b01, accB23 = b1b23;
        #pragma unroll
        for (int s = 0; s < 4; s++) {
            #pragma unroll
            for (int r = 0; r < 4; r++) {
                const float v1 = __shfl_sync(0xffffffffu, rh[r], s, 4);
                const float v2 = __shfl_sync(0xffffffffu, sh[r], s, 4);
                const unsigned long long vv1 = pack2(v1, v1);
                const unsigned long long vv2 = pack2(v2, v2);
                const int row = (s * 4 + r) * 16 + g4;
                const ulonglong2 wa = *(const ulonglong2*)(sW1a + row);
                const ulonglong2 wb = *(const ulonglong2*)(sW1b + row);
                accA01 = fma2(vv1, wa.x, accA01);
                accA23 = fma2(vv1, wa.y, accA23);
                accB01 = fma2(vv2, wb.x, accB01);
                accB23 = fma2(vv2, wb.y, accB23);
            }
        }
        // layer 2: p = base + sum w2eff * r'
        float a0, a1, a2, a3, bb0, bb1, bb2, bb3;
        unpack2(accA01, a0, a1); unpack2(accA23, a2, a3);
        unpack2(accB01, bb0, bb1); unpack2(accB23, bb2, bb3);
        float p1 = basea, p2 = baseb;
        p1 = fmaf(tanh_r(a0),  w2m2a[0], p1);
        p2 = fmaf(tanh_r(bb0), w2m2b[0], p2);
        p1 = fmaf(tanh_r(a1),  w2m2a[1], p1);
        p2 = fmaf(tanh_r(bb1), w2m2b[1], p2);
        p1 = fmaf(tanh_r(a2),  w2m2a[2], p1);
        p2 = fmaf(tanh_r(bb2), w2m2b[2], p2);
        p1 = fmaf(tanh_r(a3),  w2m2a[3], p1);
        p2 = fmaf(tanh_r(bb3), w2m2b[3], p2);
        p1 += __shfl_xor_sync(0xffffffffu, p1, 1, 4);
        p2 += __shfl_xor_sync(0xffffffffu, p2, 1, 4);
        p1 += __shfl_xor_sync(0xffffffffu, p1, 2, 4);
        p2 += __shfl_xor_sync(0xffffffffu, p2, 2, 4);
        d0 = fmaf(-0.1f, c0, uc) - p1;
        d1 = fmaf(kr, p1, fmaf(-3.0f, p2, fmaf(-0.1f, c1, kb)));
        d2 = fmaf(-0.1f, c2, kb) + p2;
    };

    #pragma unroll 1
    for (int t = 0; t < TSEQ; t++) {
        // Emit pre-update state (scan collects x_t before the step).
        if (g == 0)      ybase[t] = make_float2(x0, x1);
        else if (g == 1) xbase[t * 3 + 0] = x0;
        else if (g == 2) xbase[t * 3 + 1] = x1;
        else             xbase[t * 3 + 2] = x2;

        uc = fmaf(ku, __ldg(&ue[t]), kc);

        float a0, a1, a2, d0, d1, d2, s0, s1, s2;
        fxu(x0, x1, x2, a0, a1, a2);                               // k1
        s0 = fmaf(0.5f, a0, x0); s1 = fmaf(0.5f, a1, x1); s2 = fmaf(0.5f, a2, x2);
        fxu(s0, s1, s2, d0, d1, d2);                               // k2
        a0 = fmaf(2.0f, d0, a0); a1 = fmaf(2.0f, d1, a1); a2 = fmaf(2.0f, d2, a2);
        s0 = fmaf(0.5f, d0, x0); s1 = fmaf(0.5f, d1, x1); s2 = fmaf(0.5f, d2, x2);
        fxu(s0, s1, s2, d0, d1, d2);                               // k3
        a0 = fmaf(2.0f, d0, a0); a1 = fmaf(2.0f, d1, a1); a2 = fmaf(2.0f, d2, a2);
        s0 = x0 + d0; s1 = x1 + d1; s2 = x2 + d2;
        fxu(s0, s1, s2, d0, d1, d2);                               // k4
        a0 += d0; a1 += d1; a2 += d2;
        const float c6 = 1.0f / 6.0f;
        x0 = fmaf(c6, a0, x0); x1 = fmaf(c6, a1, x1); x2 = fmaf(c6, a2, x2);
    }
}

extern "C" void kernel_launch(void* const* d_in, const int* in_sizes, int n_in,
                              void* d_out, int out_size) {
    (void)in_sizes; (void)n_in; (void)out_size;
    reac_kernel<<<128, 128>>>(
        (const float*)d_in[0],  (const float*)d_in[1],
        (const float*)d_in[2],  (const float*)d_in[3],
        (const float*)d_in[4],  (const float*)d_in[5],
        (const float*)d_in[6],  (const float*)d_in[7],
        (const float*)d_in[8],  (const float*)d_in[9],
        (const float*)d_in[10], (const float*)d_in[11],
        (const float*)d_in[12], (const float*)d_in[13],
        (const float*)d_in[14], (const float*)d_in[15],
        (const float*)d_in[16], (const float*)d_in[17],
        (float*)d_out);
}